// round 1
// baseline (speedup 1.0000x reference)
#include <cuda_runtime.h>
#include <math.h>

// Problem constants (fixed by setup_inputs)
#define HID   64
#define NPT   128
#define LBF   (-5.0f)
#define BPB   8      // batches per block

// Dynamic SMEM layout:
//   w2s : [2][64][64]  transposed: w2s[d][k*64 + j] = W2_d[j][k]   (32768 B)
//   h1s : [64][128]    h1s[k*128 + p]                              (32768 B)
#define SMEM_BYTES (65536)

__global__ __launch_bounds__(256)
void mono_mlp_kernel(const float* __restrict__ z,  const float* __restrict__ u,
                     const float* __restrict__ w01, const float* __restrict__ b01,
                     const float* __restrict__ w02, const float* __restrict__ b02,
                     const float* __restrict__ w03, const float* __restrict__ b03,
                     const float* __restrict__ w11, const float* __restrict__ b11,
                     const float* __restrict__ w12, const float* __restrict__ b12,
                     const float* __restrict__ w13, const float* __restrict__ b13,
                     const float* __restrict__ bias, float* __restrict__ out, int B)
{
    extern __shared__ float smem[];
    float* w2s = smem;          // 2 * 4096 floats
    float* h1s = smem + 8192;   // 64 * 128 floats

    __shared__ float w1s[2][HID], b1s[2][HID], b2s[2][HID], w3s[2][HID];
    __shared__ float b3s[2], red[16];

    const int tid = threadIdx.x;

    // ---- Load weights to SMEM (once per block) ----
    for (int i = tid; i < HID * HID; i += 256) {
        int j = i >> 6, k = i & 63;          // i = j*64 + k, global W2 is [j][k]
        w2s[k * 64 + j]        = w02[i];     // transpose to k-major
        w2s[4096 + k * 64 + j] = w12[i];
    }
    if (tid < HID) {
        w1s[0][tid] = w01[tid]; w1s[1][tid] = w11[tid];
        b1s[0][tid] = b01[tid]; b1s[1][tid] = b11[tid];
        b2s[0][tid] = b02[tid]; b2s[1][tid] = b12[tid];
        w3s[0][tid] = w03[tid]; w3s[1][tid] = w13[tid];
    }
    if (tid == 0) { b3s[0] = b03[0]; b3s[1] = b13[0]; }
    __syncthreads();

    const int tx = tid & 15;   // output-tile (j) group: j = 4*tx .. 4*tx+3
    const int ty = tid >> 4;   // point-tile (p) group: p = 8*ty .. 8*ty+7
    const float biasv = bias[0];

    for (int bi = 0; bi < BPB; bi++) {
        const int b = blockIdx.x * BPB + bi;
        if (b >= B) break;
        float hz = biasv;   // only meaningful on thread 0

        #pragma unroll 1
        for (int d = 0; d < 2; d++) {
            // d_size for this (b, d)
            const float zc  = fmaxf(z[b * 2 + d], LBF);
            const float dsz = (zc - LBF) * (1.0f / (float)(NPT - 1));

            // ---- Phase A: build H1 tile (64 hid x 128 points), k-major ----
            {
                const int p  = tid & 127;
                const int k0 = (tid >> 7) * 32;
                const float uv = (p < NPT - 1) ? u[(b * 2 + d) * (NPT - 1) + p] : 0.0f;
                const float x  = fmaf(dsz, (float)p + uv, LBF);
                #pragma unroll
                for (int kk = 0; kk < 32; kk++) {
                    const int k = k0 + kk;
                    float h = fmaf(x, w1s[d][k], b1s[d][k]);
                    h = (h > 0.0f) ? h : 0.01f * h;       // LeakyReLU(0.01)
                    h1s[k * 128 + p] = h;
                }
            }
            __syncthreads();

            // ---- Phase B: register-tiled matvec batch: C(128x64) = H1ᵀ W2ᵀ ----
            float c[8][4];
            #pragma unroll
            for (int i = 0; i < 8; i++)
                #pragma unroll
                for (int j = 0; j < 4; j++) c[i][j] = 0.0f;

            const float* h1p = h1s + ty * 8;
            const float* w2p = w2s + d * 4096 + tx * 4;

            #pragma unroll 4
            for (int k = 0; k < HID; k++) {
                const float4 wj = *(const float4*)(w2p + k * 64);
                const float4 ha = *(const float4*)(h1p + k * 128);
                const float4 hb = *(const float4*)(h1p + k * 128 + 4);
                const float hp[8] = {ha.x, ha.y, ha.z, ha.w, hb.x, hb.y, hb.z, hb.w};
                const float wv[4] = {wj.x, wj.y, wj.z, wj.w};
                #pragma unroll
                for (int i = 0; i < 8; i++)
                    #pragma unroll
                    for (int j = 0; j < 4; j++)
                        c[i][j] = fmaf(hp[i], wv[j], c[i][j]);
            }

            // ---- Phase C: bias + LeakyReLU, dot w3, reduce over j, ELU, sum ----
            float w3v[4], b2v[4];
            #pragma unroll
            for (int j = 0; j < 4; j++) {
                w3v[j] = w3s[d][tx * 4 + j];
                b2v[j] = b2s[d][tx * 4 + j];
            }
            const float b3v = b3s[d];
            float acc = 0.0f;
            #pragma unroll
            for (int i = 0; i < 8; i++) {
                float s = 0.0f;
                #pragma unroll
                for (int j = 0; j < 4; j++) {
                    float h2 = c[i][j] + b2v[j];
                    h2 = (h2 > 0.0f) ? h2 : 0.01f * h2;   // LeakyReLU(0.01)
                    s = fmaf(h2, w3v[j], s);
                }
                // reduce across 16 lanes holding the same point
                s += __shfl_down_sync(0xffffffffu, s, 8, 16);
                s += __shfl_down_sync(0xffffffffu, s, 4, 16);
                s += __shfl_down_sync(0xffffffffu, s, 2, 16);
                s += __shfl_down_sync(0xffffffffu, s, 1, 16);
                if (tx == 0) {
                    const float e = s + b3v;
                    const float o = (e > 0.0f) ? e : expm1f(e);   // ELU
                    acc += o + 1.0f;
                }
            }
            if (tx == 0) red[ty] = acc;
            __syncthreads();
            if (tid == 0) {
                float t = 0.0f;
                #pragma unroll
                for (int i = 0; i < 16; i++) t += red[i];
                hz = fmaf(t, dsz, hz);
            }
            __syncthreads();   // protects red + h1s for next iteration
        }
        if (tid == 0) out[b] = hz;
    }
}

extern "C" void kernel_launch(void* const* d_in, const int* in_sizes, int n_in,
                              void* d_out, int out_size)
{
    const float* z   = (const float*)d_in[0];
    const float* u   = (const float*)d_in[1];
    const float* w01 = (const float*)d_in[2];
    const float* b01 = (const float*)d_in[3];
    const float* w02 = (const float*)d_in[4];
    const float* b02 = (const float*)d_in[5];
    const float* w03 = (const float*)d_in[6];
    const float* b03 = (const float*)d_in[7];
    const float* w11 = (const float*)d_in[8];
    const float* b11 = (const float*)d_in[9];
    const float* w12 = (const float*)d_in[10];
    const float* b12 = (const float*)d_in[11];
    const float* w13 = (const float*)d_in[12];
    const float* b13 = (const float*)d_in[13];
    const float* bias= (const float*)d_in[14];
    float* out = (float*)d_out;

    const int B = in_sizes[0] / 2;

    cudaFuncSetAttribute(mono_mlp_kernel,
                         cudaFuncAttributeMaxDynamicSharedMemorySize, SMEM_BYTES);

    const int grid = (B + BPB - 1) / BPB;
    mono_mlp_kernel<<<grid, 256, SMEM_BYTES>>>(
        z, u, w01, b01, w02, b02, w03, b03,
        w11, b11, w12, b12, w13, b13, bias, out, B);
}

// round 2
// speedup vs baseline: 3.7384x; 3.7384x over previous
#include <cuda_runtime.h>
#include <math.h>

// Problem constants (fixed by setup_inputs)
#define HID   64
#define NPT   128
#define LBF   (-5.0f)
#define BPB   8      // batches per block

// SMEM: B-fragments for W2^T, pre-converted to tf32, in mma fragment order.
// bfrag[d][kt][nt][lane] = { W2_d[n][8kt+tig], W2_d[n][8kt+tig+4] }, n = 8nt + (lane>>2)
__device__ __forceinline__ unsigned f2tf32(float x) {
    unsigned r;
    asm("cvt.rna.tf32.f32 %0, %1;\n" : "=r"(r) : "f"(x));
    return r;
}

__device__ __forceinline__ void mma_tf32(float c[4],
                                         unsigned a0, unsigned a1, unsigned a2, unsigned a3,
                                         unsigned b0, unsigned b1) {
    asm volatile(
        "mma.sync.aligned.m16n8k8.row.col.f32.tf32.tf32.f32 "
        "{%0,%1,%2,%3}, {%4,%5,%6,%7}, {%8,%9}, {%0,%1,%2,%3};\n"
        : "+f"(c[0]), "+f"(c[1]), "+f"(c[2]), "+f"(c[3])
        : "r"(a0), "r"(a1), "r"(a2), "r"(a3), "r"(b0), "r"(b1));
}

__global__ __launch_bounds__(256)
void mono_mlp_tc_kernel(const float* __restrict__ z,  const float* __restrict__ u,
                        const float* __restrict__ w01, const float* __restrict__ b01,
                        const float* __restrict__ w02, const float* __restrict__ b02,
                        const float* __restrict__ w03, const float* __restrict__ b03,
                        const float* __restrict__ w11, const float* __restrict__ b11,
                        const float* __restrict__ w12, const float* __restrict__ b12,
                        const float* __restrict__ w13, const float* __restrict__ b13,
                        const float* __restrict__ bias, float* __restrict__ out, int B)
{
    __shared__ uint2  bfrag[2 * 8 * 8 * 32];   // 32 KB, tf32-packed B fragments
    __shared__ float2 w1b1[2][HID];            // (w1[k], b1[k])
    __shared__ float2 w3b2[2][HID];            // (w3[j], b2[j])
    __shared__ float  b3s[2];
    __shared__ float  red[8];

    const int tid = threadIdx.x;

    // ---- Build B fragments (once per block) ----
    for (int e = tid; e < 2 * 8 * 8 * 32; e += 256) {
        const int lane = e & 31;
        const int nt   = (e >> 5) & 7;
        const int kt   = (e >> 8) & 7;
        const int d    = (e >> 11) & 1;
        const int n    = 8 * nt + (lane >> 2);
        const int k    = 8 * kt + (lane & 3);
        const float* w2 = d ? w12 : w02;
        bfrag[e] = make_uint2(f2tf32(w2[n * 64 + k]), f2tf32(w2[n * 64 + k + 4]));
    }
    if (tid < HID) {
        w1b1[0][tid] = make_float2(w01[tid], b01[tid]);
        w1b1[1][tid] = make_float2(w11[tid], b11[tid]);
        w3b2[0][tid] = make_float2(w03[tid], b02[tid]);
        w3b2[1][tid] = make_float2(w13[tid], b12[tid]);
    }
    if (tid == 0) { b3s[0] = b03[0]; b3s[1] = b13[0]; }
    __syncthreads();

    const int warp = tid >> 5;
    const int lane = tid & 31;
    const int gid  = lane >> 2;   // group id (row within m16 tile)
    const int tig  = lane & 3;    // thread-in-group (k / col selector)
    const int p0   = 16 * warp + gid;   // point rows owned by this thread
    const int p1   = p0 + 8;
    const float biasv = bias[0];

    for (int bi = 0; bi < BPB; bi++) {
        const int b = blockIdx.x * BPB + bi;
        if (b >= B) break;
        float hz = biasv;   // meaningful on thread 0 only

        #pragma unroll 1
        for (int d = 0; d < 2; d++) {
            const float zc  = fmaxf(z[b * 2 + d], LBF);
            const float dsz = (zc - LBF) * (1.0f / (float)(NPT - 1));
            const int   ub  = (b * 2 + d) * (NPT - 1);

            // x at this thread's two point-rows (layer-0 input)
            const float u0 = u[ub + p0];                          // p0 <= 119 always valid
            const float u1 = (p1 < NPT - 1) ? u[ub + p1] : 0.0f;  // p1 can be 127
            const float x0 = fmaf(dsz, (float)p0 + u0, LBF);
            const float x1 = fmaf(dsz, (float)p1 + u1, LBF);

            // ---- layer-2 GEMM: C(16 x 64 per warp) = H1 x W2^T, K=64, tf32 mma ----
            float acc[8][4];
            #pragma unroll
            for (int nt = 0; nt < 8; nt++)
                #pragma unroll
                for (int q = 0; q < 4; q++) acc[nt][q] = 0.0f;

            const uint2* bfr = &bfrag[(d * 64) * 32 + lane];

            #pragma unroll
            for (int kt = 0; kt < 8; kt++) {
                // A fragment: layer-1 hidden values at (p0/p1, k = 8kt+tig / +4)
                const float2 wa = w1b1[d][8 * kt + tig];
                const float2 wb = w1b1[d][8 * kt + tig + 4];
                float h00 = fmaf(x0, wa.x, wa.y); h00 = (h00 > 0.f) ? h00 : 0.01f * h00;
                float h10 = fmaf(x1, wa.x, wa.y); h10 = (h10 > 0.f) ? h10 : 0.01f * h10;
                float h01 = fmaf(x0, wb.x, wb.y); h01 = (h01 > 0.f) ? h01 : 0.01f * h01;
                float h11 = fmaf(x1, wb.x, wb.y); h11 = (h11 > 0.f) ? h11 : 0.01f * h11;
                const unsigned a0 = f2tf32(h00), a1 = f2tf32(h10);
                const unsigned a2 = f2tf32(h01), a3 = f2tf32(h11);

                #pragma unroll
                for (int nt = 0; nt < 8; nt++) {
                    const uint2 bf = bfr[(kt * 8 + nt) * 32];
                    mma_tf32(acc[nt], a0, a1, a2, a3, bf.x, bf.y);
                }
            }

            // ---- epilogue: bias + LeakyReLU, dot w3, per-point ELU, sum ----
            float s0 = 0.0f, s1 = 0.0f;   // row sums for p0, p1
            #pragma unroll
            for (int nt = 0; nt < 8; nt++) {
                const int j0 = 8 * nt + 2 * tig;
                const float2 e0 = w3b2[d][j0];
                const float2 e1 = w3b2[d][j0 + 1];
                float h;
                h = acc[nt][0] + e0.y; h = (h > 0.f) ? h : 0.01f * h; s0 = fmaf(h, e0.x, s0);
                h = acc[nt][1] + e1.y; h = (h > 0.f) ? h : 0.01f * h; s0 = fmaf(h, e1.x, s0);
                h = acc[nt][2] + e0.y; h = (h > 0.f) ? h : 0.01f * h; s1 = fmaf(h, e0.x, s1);
                h = acc[nt][3] + e1.y; h = (h > 0.f) ? h : 0.01f * h; s1 = fmaf(h, e1.x, s1);
            }
            // reduce the 4-lane k-groups (lanes gid*4 + 0..3 hold partial j-sums)
            s0 += __shfl_xor_sync(0xffffffffu, s0, 1);
            s0 += __shfl_xor_sync(0xffffffffu, s0, 2);
            s1 += __shfl_xor_sync(0xffffffffu, s1, 1);
            s1 += __shfl_xor_sync(0xffffffffu, s1, 2);

            float contrib = 0.0f;
            if (tig == 0) {
                const float b3v = b3s[d];
                float e = s0 + b3v;
                contrib  = (e > 0.f) ? e : expm1f(e);
                e = s1 + b3v;
                contrib += (e > 0.f) ? e : expm1f(e);
                contrib += 2.0f;
            }
            // warp total over its 16 points (nonzero only on lanes % 4 == 0)
            contrib += __shfl_xor_sync(0xffffffffu, contrib, 4);
            contrib += __shfl_xor_sync(0xffffffffu, contrib, 8);
            contrib += __shfl_xor_sync(0xffffffffu, contrib, 16);

            if (lane == 0) red[warp] = contrib;
            __syncthreads();
            if (tid == 0) {
                float t = 0.0f;
                #pragma unroll
                for (int w = 0; w < 8; w++) t += red[w];
                hz = fmaf(t, dsz, hz);
            }
            __syncthreads();
        }
        if (tid == 0) out[b] = hz;
    }
}

extern "C" void kernel_launch(void* const* d_in, const int* in_sizes, int n_in,
                              void* d_out, int out_size)
{
    const float* z   = (const float*)d_in[0];
    const float* u   = (const float*)d_in[1];
    const float* w01 = (const float*)d_in[2];
    const float* b01 = (const float*)d_in[3];
    const float* w02 = (const float*)d_in[4];
    const float* b02 = (const float*)d_in[5];
    const float* w03 = (const float*)d_in[6];
    const float* b03 = (const float*)d_in[7];
    const float* w11 = (const float*)d_in[8];
    const float* b11 = (const float*)d_in[9];
    const float* w12 = (const float*)d_in[10];
    const float* b12 = (const float*)d_in[11];
    const float* w13 = (const float*)d_in[12];
    const float* b13 = (const float*)d_in[13];
    const float* bias= (const float*)d_in[14];
    float* out = (float*)d_out;

    const int B = in_sizes[0] / 2;
    const int grid = (B + BPB - 1) / BPB;
    mono_mlp_tc_kernel<<<grid, 256>>>(
        z, u, w01, b01, w02, b02, w03, b03,
        w11, b11, w12, b12, w13, b13, bias, out, B);
}